// round 9
// baseline (speedup 1.0000x reference)
#include <cuda_runtime.h>
#include <cstdint>

// PSRoIPool via per-(plane,batch) smem integral image, fused row scan.
// x (4, 1029, 96, 96) fp32, rois (512,5) fp32, out (512, 21, 7, 7) fp32.
// Grid (1029, 4): block = one plane p of one batch b.
//  - Stage+row-scan: each warp owns 12 rows; loads 3×32 chunks from global
//    (each chunk = one 128B line), Kogge-Stone shuffle scan in registers,
//    single STS per element (staging store IS the row-prefix store).
//  - Col scan: each warp owns 12 columns, shuffle scan over 3 chunks of 32
//    rows (stride-97 smem, conflict-free).
//  - Gather: 4-corner difference per roi of batch b.
//
// NUMERIC CONTRACT (verified R5): bin sizes are reciprocal-multiplies
// __fmul_rn(extent, fl(1/7)) — NOT divisions. Do not change.

#define C_TOT   1029
#define PH      7
#define PW      7
#define HH      96
#define WW      96
#define WP      97            // padded row stride (conflict-free col access)
#define PLANE   (HH*WW)
#define KROIS   512
#define NBATCH  4
#define SCALE   0.0625f
#define RCP7    0.1428571492433547973632812500f   // fl(1/7) = 0x3E124925
#define THREADS 256

__device__ __forceinline__ float wscan(float v, int lane)
{
    #pragma unroll
    for (int o = 1; o < 32; o <<= 1) {
        float t = __shfl_up_sync(0xffffffffu, v, o);
        if (lane >= o) v += t;
    }
    return v;
}

__device__ __forceinline__ float corner(const float* __restrict__ S, int a, int b)
{
    return (a > 0 && b > 0) ? S[(a - 1) * WP + (b - 1)] : 0.0f;
}

__global__ __launch_bounds__(THREADS) void psroi_integral2(
    const float* __restrict__ x,
    const float* __restrict__ rois,
    float* __restrict__ out)
{
    __shared__ float sp[HH * WP];          // 37248 B
    const int p    = blockIdx.x;           // plane/channel 0..1028
    const int b    = blockIdx.y;           // batch 0..3
    const int ij   = p % (PH * PW);
    const int i    = ij / PW;
    const int j    = ij - i * PW;
    const int tid  = threadIdx.x;
    const int w    = tid >> 5;
    const int lane = tid & 31;

    // ---- Stage + row prefix (fused). Warp w owns rows 12w .. 12w+11. ----
    const float* __restrict__ plane = x + ((size_t)b * C_TOT + p) * PLANE;
    #pragma unroll 2
    for (int rr = 0; rr < 12; ++rr) {
        const int row = w * 12 + rr;
        const float* __restrict__ rp = plane + row * WW;
        float v0 = __ldg(rp + lane);
        float v1 = __ldg(rp + 32 + lane);
        float v2 = __ldg(rp + 64 + lane);
        v0 = wscan(v0, lane);
        float c0 = __shfl_sync(0xffffffffu, v0, 31);
        v1 = wscan(v1, lane) + c0;
        float c1 = __shfl_sync(0xffffffffu, v1, 31);
        v2 = wscan(v2, lane) + c1;
        float* sr = sp + row * WP;
        sr[lane]      = v0;
        sr[32 + lane] = v1;
        sr[64 + lane] = v2;
    }
    __syncthreads();

    // ---- Column prefix. Warp w owns columns 12w .. 12w+11. ----
    #pragma unroll 2
    for (int cc = 0; cc < 12; ++cc) {
        const int col = w * 12 + cc;
        float u0 = sp[(lane)      * WP + col];
        float u1 = sp[(32 + lane) * WP + col];
        float u2 = sp[(64 + lane) * WP + col];
        u0 = wscan(u0, lane);
        float d0 = __shfl_sync(0xffffffffu, u0, 31);
        u1 = wscan(u1, lane) + d0;
        float d1 = __shfl_sync(0xffffffffu, u1, 31);
        u2 = wscan(u2, lane) + d1;
        sp[(lane)      * WP + col] = u0;
        sp[(32 + lane) * WP + col] = u1;
        sp[(64 + lane) * WP + col] = u2;
    }
    __syncthreads();

    // ---- Gather: rois k = tid, tid+256 belonging to batch b. ----
    #pragma unroll
    for (int t = 0; t < 2; ++t) {
        const int k = tid + t * THREADS;
        const float* roi = rois + k * 5;
        if ((int)roi[0] != b) continue;
        int sw = (int)floorf(__fmaf_rn(roi[1], SCALE, 0.5f));
        int sh = (int)floorf(__fmaf_rn(roi[2], SCALE, 0.5f));
        int ew = (int)floorf(__fmaf_rn(roi[3], SCALE, 0.5f));
        int eh = (int)floorf(__fmaf_rn(roi[4], SCALE, 0.5f));
        float bin_h = __fmul_rn((float)max(eh - sh, 1), RCP7);
        float bin_w = __fmul_rn((float)max(ew - sw, 1), RCP7);
        int hs = min(max((int)floorf(__fmul_rn((float)i,       bin_h)) + sh, 0), HH);
        int he = min(max((int)ceilf (__fmul_rn((float)(i + 1), bin_h)) + sh, 0), HH);
        int ws = min(max((int)floorf(__fmul_rn((float)j,       bin_w)) + sw, 0), WW);
        int we = min(max((int)ceilf (__fmul_rn((float)(j + 1), bin_w)) + sw, 0), WW);

        const int area = (he - hs) * (we - ws);
        float val = 0.0f;
        if (area > 0) {
            float bin_sum = corner(sp, he, we) - corner(sp, hs, we)
                          - corner(sp, he, ws) + corner(sp, hs, ws);
            val = __fdiv_rn(bin_sum, (float)area);
        }
        out[k * C_TOT + p] = val;
    }
}

extern "C" void kernel_launch(void* const* d_in, const int* in_sizes, int n_in,
                              void* d_out, int out_size)
{
    const float* x;
    const float* rois;
    if (n_in >= 2 && in_sizes[0] == KROIS * 5) {
        rois = (const float*)d_in[0];
        x    = (const float*)d_in[1];
    } else {
        x    = (const float*)d_in[0];
        rois = (const float*)d_in[1];
    }
    float* out = (float*)d_out;

    dim3 grid(C_TOT, NBATCH);
    psroi_integral2<<<grid, THREADS>>>(x, rois, out);
}

// round 10
// speedup vs baseline: 1.6595x; 1.6595x over previous
#include <cuda_runtime.h>
#include <cstdint>

// PSRoIPool, quad-per-output (4 lanes): x (4, 1029, 96, 96) fp32,
// rois (512,5) fp32, out (512, 21, 7, 7) fp32.
// Flat out idx = k*1029 + r; input channel = r; bin i=(r%49)/7, j=r%7.
// Each 4-lane quad computes one output: lanes stripe window columns
// (4 contiguous floats -> 1-2 sectors per row-step), rows in outer loop,
// then 2-step intra-quad butterfly reduce.
//
// NUMERIC CONTRACT (verified R5): bin sizes are reciprocal-multiplies
// __fmul_rn(extent, fl(1/7)) — NOT divisions. Do not change.

#define C_TOT   1029
#define PH      7
#define PW      7
#define HH      96
#define WW      96
#define PLANE   (HH*WW)
#define KROIS   512
#define SCALE   0.0625f
#define RCP7    0.1428571492433547973632812500f   // fl(1/7) = 0x3E124925
#define TOTAL   (KROIS * C_TOT)                   // 526848
#define THREADS 256
#define QPB     (THREADS / 4)                     // quads per block = 64

__global__ __launch_bounds__(THREADS) void psroi_quad(
    const float* __restrict__ x,
    const float* __restrict__ rois,
    float* __restrict__ out)
{
    const int qidx = blockIdx.x * QPB + (threadIdx.x >> 2);   // output index
    const int ql   = threadIdx.x & 3;                         // lane in quad
    if (qidx >= TOTAL) return;

    const int k  = qidx / C_TOT;
    const int r  = qidx - k * C_TOT;
    const int ij = r % (PH * PW);
    const int i  = ij / PW;
    const int j  = ij - i * PW;

    // Quad-uniform roi decode (replicated x4; cheap).
    const float* roi = rois + k * 5;
    const int b  = (int)roi[0];
    const int sw = (int)floorf(__fmaf_rn(roi[1], SCALE, 0.5f));
    const int sh = (int)floorf(__fmaf_rn(roi[2], SCALE, 0.5f));
    const int ew = (int)floorf(__fmaf_rn(roi[3], SCALE, 0.5f));
    const int eh = (int)floorf(__fmaf_rn(roi[4], SCALE, 0.5f));

    const float bin_h = __fmul_rn((float)max(eh - sh, 1), RCP7);
    const float bin_w = __fmul_rn((float)max(ew - sw, 1), RCP7);

    const int hs = min(max((int)floorf(__fmul_rn((float)i,       bin_h)) + sh, 0), HH);
    const int he = min(max((int)ceilf (__fmul_rn((float)(i + 1), bin_h)) + sh, 0), HH);
    const int ws = min(max((int)floorf(__fmul_rn((float)j,       bin_w)) + sw, 0), WW);
    const int we = min(max((int)ceilf (__fmul_rn((float)(j + 1), bin_w)) + sw, 0), WW);

    const int wwid = we - ws;
    const int area = (he - hs) * wwid;

    float s = 0.0f;
    if (area > 0) {
        const float* __restrict__ win =
            x + ((size_t)b * C_TOT + r) * PLANE + hs * WW + ws;
        for (int hy = 0; hy < he - hs; ++hy) {
            const float* __restrict__ row = win + hy * WW;
            // Lanes stripe columns: 4 contiguous floats per step.
            for (int wx = ql; wx < wwid; wx += 4)
                s += __ldg(row + wx);
        }
    }

    // Intra-quad butterfly (xor 1, 2 stay within the quad).
    s += __shfl_xor_sync(0xffffffffu, s, 1);
    s += __shfl_xor_sync(0xffffffffu, s, 2);

    if (ql == 0)
        out[qidx] = (area > 0) ? __fdiv_rn(s, (float)area) : 0.0f;
}

extern "C" void kernel_launch(void* const* d_in, const int* in_sizes, int n_in,
                              void* d_out, int out_size)
{
    const float* x;
    const float* rois;
    if (n_in >= 2 && in_sizes[0] == KROIS * 5) {
        rois = (const float*)d_in[0];
        x    = (const float*)d_in[1];
    } else {
        x    = (const float*)d_in[0];
        rois = (const float*)d_in[1];
    }
    float* out = (float*)d_out;

    const int blocks = (TOTAL + QPB - 1) / QPB;   // 8232
    psroi_quad<<<blocks, THREADS>>>(x, rois, out);
}